// round 12
// baseline (speedup 1.0000x reference)
#include <cuda_runtime.h>
#include <cuda_bf16.h>
#include <cstdint>

// Problem shape (fixed): M = B*S = 4096, K = IN = 4096, N = OUT = 4096
#define KDIM 4096
#define NDIM 4096

#define BM 256
#define BN 128
#define BK 64
#define LDA 72      // BK + 8 halves pad -> 144B row stride, conflict-free for ldmatrix
#define NTHREADS 256
#define NSTAGES 4

#define TILE_A (BM * LDA)                  // 18432 halves
#define TILE_B (BN * LDA)                  // 9216 halves
#define STAGE_HALVES (TILE_A + TILE_B)     // 27648 halves = 55296 B
#define SMEM_BYTES (NSTAGES * STAGE_HALVES * 2)   // 221184 B, 1 CTA/SM

// Scratch: converted bf16 operands (device globals, not runtime allocs)
__device__ __nv_bfloat16 g_x_bf16[4096 * KDIM];
__device__ __nv_bfloat16 g_w_bf16[NDIM * KDIM];

// ---------------------------------------------------------------------------
// Merged preprocess: x (f32)->bf16 and w (f32)*scale->bf16 in ONE kernel
// ---------------------------------------------------------------------------
__global__ void convert_all_kernel(const float* __restrict__ x,
                                   const float* __restrict__ w,
                                   const float* __restrict__ scale,
                                   int c4x, int total4) {
    int i = blockIdx.x * blockDim.x + threadIdx.x;
    if (i >= total4) return;
    if (i < c4x) {
        float4 v = reinterpret_cast<const float4*>(x)[i];
        __nv_bfloat162 lo = __floats2bfloat162_rn(v.x, v.y);
        __nv_bfloat162 hi = __floats2bfloat162_rn(v.z, v.w);
        uint2 p;
        p.x = *reinterpret_cast<unsigned*>(&lo);
        p.y = *reinterpret_cast<unsigned*>(&hi);
        reinterpret_cast<uint2*>(g_x_bf16)[i] = p;
    } else {
        int j = i - c4x;
        int o = (j * 4) / KDIM;          // all 4 elems share a row (KDIM % 4 == 0)
        __nv_bfloat16 s = __float2bfloat16(scale[o]);
        float4 v = reinterpret_cast<const float4*>(w)[j];
        __nv_bfloat16 h0 = __hmul(__float2bfloat16(v.x), s);
        __nv_bfloat16 h1 = __hmul(__float2bfloat16(v.y), s);
        __nv_bfloat16 h2 = __hmul(__float2bfloat16(v.z), s);
        __nv_bfloat16 h3 = __hmul(__float2bfloat16(v.w), s);
        __nv_bfloat162 lo = __halves2bfloat162(h0, h1);
        __nv_bfloat162 hi = __halves2bfloat162(h2, h3);
        uint2 p;
        p.x = *reinterpret_cast<unsigned*>(&lo);
        p.y = *reinterpret_cast<unsigned*>(&hi);
        reinterpret_cast<uint2*>(g_w_bf16)[j] = p;
    }
}

// ---------------------------------------------------------------------------
// GEMM: C[M,N] = A[M,K] @ B[N,K]^T, bf16 in / f32 accum / f32 out (bf16-rounded)
// 256x128 CTA tile (-25% L2 traffic vs 128x128), 64x64 warp tiles, 4-stage
// cp.async ring, FRAGMENT DOUBLE-BUFFER, 1 CTA/SM, 256 threads.
// ---------------------------------------------------------------------------
__device__ __forceinline__ void cp_async16(void* smem_ptr, const void* gmem_ptr) {
    unsigned saddr = (unsigned)__cvta_generic_to_shared(smem_ptr);
    asm volatile("cp.async.cg.shared.global [%0], [%1], 16;\n" :: "r"(saddr), "l"(gmem_ptr));
}
__device__ __forceinline__ void cp_async_commit() {
    asm volatile("cp.async.commit_group;\n");
}
template <int N>
__device__ __forceinline__ void cp_async_wait() {
    asm volatile("cp.async.wait_group %0;\n" :: "n"(N));
}
__device__ __forceinline__ void ldmatrix_x4(unsigned& r0, unsigned& r1, unsigned& r2,
                                            unsigned& r3, const void* smem_ptr) {
    unsigned saddr = (unsigned)__cvta_generic_to_shared(smem_ptr);
    asm volatile("ldmatrix.sync.aligned.m8n8.x4.shared.b16 {%0,%1,%2,%3}, [%4];\n"
                 : "=r"(r0), "=r"(r1), "=r"(r2), "=r"(r3) : "r"(saddr));
}
__device__ __forceinline__ void mma_16816(float* c, const unsigned* a, const unsigned* b) {
    asm volatile(
        "mma.sync.aligned.m16n8k16.row.col.f32.bf16.bf16.f32 "
        "{%0,%1,%2,%3}, {%4,%5,%6,%7}, {%8,%9}, {%0,%1,%2,%3};\n"
        : "+f"(c[0]), "+f"(c[1]), "+f"(c[2]), "+f"(c[3])
        : "r"(a[0]), "r"(a[1]), "r"(a[2]), "r"(a[3]), "r"(b[0]), "r"(b[1]));
}

__global__ void __launch_bounds__(NTHREADS, 1)
gemm_bf16_kernel(const float* __restrict__ bias, float* __restrict__ out, int M) {
    extern __shared__ __align__(16) __nv_bfloat16 smem[];
    // stage s: A at smem[s*STAGE_HALVES], B at +TILE_A

    const int tid  = threadIdx.x;
    const int wid  = tid >> 5;
    const int lane = tid & 31;
    const int grp  = lane >> 3;       // 0..3 (ldmatrix address group)
    const int rin  = lane & 7;

    const int m0 = blockIdx.y * BM;
    const int n0 = blockIdx.x * BN;

    // warp tiling: 4 (m) x 2 (n) warps; each warp covers 64(m) x 64(n)
    const int warp_m = (wid & 3) * 64;
    const int warp_n = (wid >> 2) * 64;

    const __nv_bfloat16* A = g_x_bf16;
    const __nv_bfloat16* B = g_w_bf16;

    float acc[4][8][4];   // [mtile 16][ntile 8][frag] = 128 regs
#pragma unroll
    for (int i = 0; i < 4; i++)
#pragma unroll
        for (int j = 0; j < 8; j++)
#pragma unroll
            for (int r = 0; r < 4; r++) acc[i][j][r] = 0.0f;

    const int KTILES = KDIM / BK;   // 64

    // loader: A 2048 chunks (8/thread), B 1024 chunks (4/thread), 16B each
    auto load_tile = [&](int stage, int kt) {
        __nv_bfloat16* sA = smem + stage * STAGE_HALVES;
        __nv_bfloat16* sB = sA + TILE_A;
#pragma unroll
        for (int j = 0; j < 8; j++) {
            int chunk = tid + j * NTHREADS;          // 0..2047
            int row = chunk >> 3;                    // 0..255
            int kc  = chunk & 7;
            cp_async16(&sA[row * LDA + kc * 8],
                       &A[(size_t)(m0 + row) * KDIM + kt * BK + kc * 8]);
        }
#pragma unroll
        for (int j = 0; j < 4; j++) {
            int chunk = tid + j * NTHREADS;          // 0..1023
            int row = chunk >> 3;                    // 0..127
            int kc  = chunk & 7;
            cp_async16(&sB[row * LDA + kc * 8],
                       &B[(size_t)(n0 + row) * KDIM + kt * BK + kc * 8]);
        }
    };

    // fragment loader for one ks (16-wide k slice)
    auto load_frags = [&](const __nv_bfloat16* a_s, const __nv_bfloat16* b_s,
                          int kbase, unsigned af[4][4], unsigned bf[8][2]) {
#pragma unroll
        for (int mt = 0; mt < 4; mt++) {
            int r = warp_m + mt * 16 + (grp & 1) * 8 + rin;
            int c = kbase + (grp >> 1) * 8;
            ldmatrix_x4(af[mt][0], af[mt][1], af[mt][2], af[mt][3], &a_s[r * LDA + c]);
        }
#pragma unroll
        for (int p = 0; p < 4; p++) {
            int nrow = warp_n + p * 16 + (grp >> 1) * 8 + rin;
            int c = kbase + (grp & 1) * 8;
            ldmatrix_x4(bf[2 * p][0], bf[2 * p][1],
                        bf[2 * p + 1][0], bf[2 * p + 1][1], &b_s[nrow * LDA + c]);
        }
    };

    // prologue: 3 tiles in flight
    load_tile(0, 0); cp_async_commit();
    load_tile(1, 1); cp_async_commit();
    load_tile(2, 2); cp_async_commit();

    unsigned afrag[2][4][4];
    unsigned bfrag[2][8][2];

    int stage = 0;
    for (int kt = 0; kt < KTILES; kt++) {
        if (kt + 1 < KTILES) cp_async_wait<2>();
        else                 cp_async_wait<0>();
        __syncthreads();    // tile kt ready; stage (kt+3)%4 free for reuse

        if (kt + 3 < KTILES) {
            load_tile((stage + 3) & 3, kt + 3);
            cp_async_commit();
        }

        const __nv_bfloat16* a_s = smem + stage * STAGE_HALVES;
        const __nv_bfloat16* b_s = a_s + TILE_A;

        // fragment double-buffered ks loop
        load_frags(a_s, b_s, 0, afrag[0], bfrag[0]);
#pragma unroll
        for (int ks = 0; ks < 4; ks++) {
            const int cur = ks & 1;
            if (ks < 3)
                load_frags(a_s, b_s, (ks + 1) * 16, afrag[cur ^ 1], bfrag[cur ^ 1]);
#pragma unroll
            for (int mt = 0; mt < 4; mt++)
#pragma unroll
                for (int nt = 0; nt < 8; nt++)
                    mma_16816(acc[mt][nt], afrag[cur][mt], bfrag[cur][nt]);
        }

        stage = (stage + 1) & 3;
    }

    // ---- epilogue: bf16-round(acc) + bf16 bias, store f32 (output dtype f32) ----
    const int tig = lane & 3;
    const int g8  = lane >> 2;
#pragma unroll
    for (int nt = 0; nt < 8; nt++) {
        int n = n0 + warp_n + nt * 8 + tig * 2;
        __nv_bfloat16 bb0 = __float2bfloat16(bias[n]);
        __nv_bfloat16 bb1 = __float2bfloat16(bias[n + 1]);
#pragma unroll
        for (int mt = 0; mt < 4; mt++) {
            int mA = m0 + warp_m + mt * 16 + g8;
            int mB = mA + 8;
            float2 v0, v1;
            v0.x = __bfloat162float(__hadd(__float2bfloat16(acc[mt][nt][0]), bb0));
            v0.y = __bfloat162float(__hadd(__float2bfloat16(acc[mt][nt][1]), bb1));
            v1.x = __bfloat162float(__hadd(__float2bfloat16(acc[mt][nt][2]), bb0));
            v1.y = __bfloat162float(__hadd(__float2bfloat16(acc[mt][nt][3]), bb1));
            *reinterpret_cast<float2*>(&out[(size_t)mA * NDIM + n]) = v0;
            *reinterpret_cast<float2*>(&out[(size_t)mB * NDIM + n]) = v1;
        }
    }
}

// ---------------------------------------------------------------------------
// Launch
// ---------------------------------------------------------------------------
extern "C" void kernel_launch(void* const* d_in, const int* in_sizes, int n_in,
                              void* d_out, int out_size) {
    const float* x     = (const float*)d_in[0];   // [B,S,IN] f32
    const float* w_fp8 = (const float*)d_in[1];   // [OUT,IN] f32
    const float* scale = (const float*)d_in[2];   // [OUT,1] f32
    const float* bias  = (const float*)d_in[3];   // [OUT] f32
    float* out         = (float*)d_out;           // [B,S,OUT] f32 (bf16-rounded values)

    int M = in_sizes[0] / KDIM;                   // 4096

    int c4x = (M * KDIM) / 4;
    int c4w = (NDIM * KDIM) / 4;
    int total4 = c4x + c4w;
    convert_all_kernel<<<(total4 + 255) / 256, 256>>>(x, w_fp8, scale, c4x, total4);

    cudaFuncSetAttribute(gemm_bf16_kernel,
                         cudaFuncAttributeMaxDynamicSharedMemorySize, SMEM_BYTES);
    dim3 grid(NDIM / BN, M / BM);   // (32, 16) = 512 CTAs
    gemm_bf16_kernel<<<grid, NTHREADS, SMEM_BYTES>>>(bias, out, M);
}

// round 13
// speedup vs baseline: 1.2232x; 1.2232x over previous
#include <cuda_runtime.h>
#include <cuda_bf16.h>
#include <cstdint>

// Problem shape (fixed): M = B*S = 4096, K = IN = 4096, N = OUT = 4096
#define KDIM 4096
#define NDIM 4096

#define BM 128
#define BN 128
#define BK 64
#define LDA 72      // BK + 8 halves pad -> 144B row stride, conflict-free for ldmatrix
#define NTHREADS 256
#define NSTAGES 3

#define TILE_HALVES (BM * LDA)                       // 9216 halves per operand tile
#define STAGE_HALVES (2 * TILE_HALVES)               // A + B per stage
#define SMEM_BYTES (NSTAGES * STAGE_HALVES * 2)      // 110592 B -> 2 CTAs/SM

// Scratch: converted bf16 operands (device globals, not runtime allocs)
__device__ __nv_bfloat16 g_x_bf16[4096 * KDIM];
__device__ __nv_bfloat16 g_w_bf16[NDIM * KDIM];

// ---------------------------------------------------------------------------
// Merged preprocess: x (f32)->bf16 and w (f32)*scale->bf16 in ONE kernel
// ---------------------------------------------------------------------------
__global__ void convert_all_kernel(const float* __restrict__ x,
                                   const float* __restrict__ w,
                                   const float* __restrict__ scale,
                                   int c4x, int total4) {
    int i = blockIdx.x * blockDim.x + threadIdx.x;
    if (i >= total4) return;
    if (i < c4x) {
        float4 v = reinterpret_cast<const float4*>(x)[i];
        __nv_bfloat162 lo = __floats2bfloat162_rn(v.x, v.y);
        __nv_bfloat162 hi = __floats2bfloat162_rn(v.z, v.w);
        uint2 p;
        p.x = *reinterpret_cast<unsigned*>(&lo);
        p.y = *reinterpret_cast<unsigned*>(&hi);
        reinterpret_cast<uint2*>(g_x_bf16)[i] = p;
    } else {
        int j = i - c4x;
        int o = (j * 4) / KDIM;          // all 4 elems share a row (KDIM % 4 == 0)
        __nv_bfloat16 s = __float2bfloat16(scale[o]);
        float4 v = reinterpret_cast<const float4*>(w)[j];
        __nv_bfloat16 h0 = __hmul(__float2bfloat16(v.x), s);
        __nv_bfloat16 h1 = __hmul(__float2bfloat16(v.y), s);
        __nv_bfloat16 h2 = __hmul(__float2bfloat16(v.z), s);
        __nv_bfloat16 h3 = __hmul(__float2bfloat16(v.w), s);
        __nv_bfloat162 lo = __halves2bfloat162(h0, h1);
        __nv_bfloat162 hi = __halves2bfloat162(h2, h3);
        uint2 p;
        p.x = *reinterpret_cast<unsigned*>(&lo);
        p.y = *reinterpret_cast<unsigned*>(&hi);
        reinterpret_cast<uint2*>(g_w_bf16)[j] = p;
    }
}

// ---------------------------------------------------------------------------
// GEMM: C[M,N] = A[M,K] @ B[N,K]^T, bf16 in / f32 accum / f32 out (bf16-rounded)
// mma.sync m16n8k16, cp.async 3-stage (BK=64), ldmatrix INTERLEAVED with mma,
// 64x32 warp tiles, 2 CTAs/SM (16 warps), one __syncthreads per k-tile.
// ---------------------------------------------------------------------------
__device__ __forceinline__ void cp_async16(void* smem_ptr, const void* gmem_ptr) {
    unsigned saddr = (unsigned)__cvta_generic_to_shared(smem_ptr);
    asm volatile("cp.async.cg.shared.global [%0], [%1], 16;\n" :: "r"(saddr), "l"(gmem_ptr));
}
__device__ __forceinline__ void cp_async_commit() {
    asm volatile("cp.async.commit_group;\n");
}
template <int N>
__device__ __forceinline__ void cp_async_wait() {
    asm volatile("cp.async.wait_group %0;\n" :: "n"(N));
}
__device__ __forceinline__ void ldmatrix_x4(unsigned& r0, unsigned& r1, unsigned& r2,
                                            unsigned& r3, const void* smem_ptr) {
    unsigned saddr = (unsigned)__cvta_generic_to_shared(smem_ptr);
    asm volatile("ldmatrix.sync.aligned.m8n8.x4.shared.b16 {%0,%1,%2,%3}, [%4];\n"
                 : "=r"(r0), "=r"(r1), "=r"(r2), "=r"(r3) : "r"(saddr));
}
__device__ __forceinline__ void mma_16816(float* c, const unsigned* a, const unsigned* b) {
    asm volatile(
        "mma.sync.aligned.m16n8k16.row.col.f32.bf16.bf16.f32 "
        "{%0,%1,%2,%3}, {%4,%5,%6,%7}, {%8,%9}, {%0,%1,%2,%3};\n"
        : "+f"(c[0]), "+f"(c[1]), "+f"(c[2]), "+f"(c[3])
        : "r"(a[0]), "r"(a[1]), "r"(a[2]), "r"(a[3]), "r"(b[0]), "r"(b[1]));
}

__global__ void __launch_bounds__(NTHREADS, 2)
gemm_bf16_kernel(const float* __restrict__ bias, float* __restrict__ out, int M) {
    extern __shared__ __align__(16) __nv_bfloat16 smem[];
    // stage s: A at smem[s*STAGE_HALVES], B at smem[s*STAGE_HALVES + TILE_HALVES]

    const int tid  = threadIdx.x;
    const int wid  = tid >> 5;
    const int lane = tid & 31;
    const int grp  = lane >> 3;       // 0..3 (ldmatrix address group)
    const int rin  = lane & 7;

    const int m0 = blockIdx.y * BM;
    const int n0 = blockIdx.x * BN;

    // warp tiling: 2 (m) x 4 (n) warps; each warp 64(m) x 32(n)
    const int warp_m = (wid >> 2) * 64;
    const int warp_n = (wid & 3) * 32;

    const __nv_bfloat16* A = g_x_bf16;
    const __nv_bfloat16* B = g_w_bf16;

    float acc[4][4][4];   // [mtile][ntile][frag]
#pragma unroll
    for (int i = 0; i < 4; i++)
#pragma unroll
        for (int j = 0; j < 4; j++)
#pragma unroll
            for (int r = 0; r < 4; r++) acc[i][j][r] = 0.0f;

    const int KTILES = KDIM / BK;   // 64

    // tile loader: 1024 16B chunks per operand; 4 chunks/thread each
    auto load_tile = [&](int stage, int kt) {
        __nv_bfloat16* sA = smem + stage * STAGE_HALVES;
        __nv_bfloat16* sB = sA + TILE_HALVES;
#pragma unroll
        for (int j = 0; j < 4; j++) {
            int chunk = tid + j * NTHREADS;          // 0..1023
            int row = chunk >> 3;                    // 0..127
            int kc  = chunk & 7;                     // 0..7
            int k   = kt * BK + kc * 8;
            cp_async16(&sA[row * LDA + kc * 8], &A[(size_t)(m0 + row) * KDIM + k]);
            cp_async16(&sB[row * LDA + kc * 8], &B[(size_t)(n0 + row) * KDIM + k]);
        }
    };

    // prologue: 2 tiles in flight
    load_tile(0, 0);
    cp_async_commit();
    load_tile(1, 1);
    cp_async_commit();

    int stage = 0;
    for (int kt = 0; kt < KTILES; kt++) {
        if (kt + 1 < KTILES) cp_async_wait<1>();
        else                 cp_async_wait<0>();
        __syncthreads();    // tile kt ready for ALL warps; stage (kt+2)%3 free for reuse

        if (kt + 2 < KTILES) {
            load_tile((stage + 2) % NSTAGES, kt + 2);
            cp_async_commit();
        }

        const __nv_bfloat16* a_s = smem + stage * STAGE_HALVES;
        const __nv_bfloat16* b_s = a_s + TILE_HALVES;

#pragma unroll
        for (int ks = 0; ks < 4; ks++) {
            const int kbase = ks * 16;
            unsigned afrag[4][4];
            unsigned bfrag[4][2];

            // ---- INTERLEAVED schedule (volatile asm order is preserved):
            // B first, then A0/A1; each later A-load is covered by 8 mmas of
            // tensor work so LSU and tensor pipes overlap within the warp.
            {
                int c = kbase + (grp & 1) * 8;
                int nrow0 = warp_n + 0 * 16 + (grp >> 1) * 8 + rin;
                ldmatrix_x4(bfrag[0][0], bfrag[0][1], bfrag[1][0], bfrag[1][1],
                            &b_s[nrow0 * LDA + c]);
                int nrow1 = warp_n + 1 * 16 + (grp >> 1) * 8 + rin;
                ldmatrix_x4(bfrag[2][0], bfrag[2][1], bfrag[3][0], bfrag[3][1],
                            &b_s[nrow1 * LDA + c]);
            }
            {
                int c = kbase + (grp >> 1) * 8;
                int r0 = warp_m + 0 * 16 + (grp & 1) * 8 + rin;
                ldmatrix_x4(afrag[0][0], afrag[0][1], afrag[0][2], afrag[0][3],
                            &a_s[r0 * LDA + c]);
                int r1 = warp_m + 1 * 16 + (grp & 1) * 8 + rin;
                ldmatrix_x4(afrag[1][0], afrag[1][1], afrag[1][2], afrag[1][3],
                            &a_s[r1 * LDA + c]);
            }
#pragma unroll
            for (int nt = 0; nt < 4; nt++) mma_16816(acc[0][nt], afrag[0], bfrag[nt]);
            {
                int c = kbase + (grp >> 1) * 8;
                int r2 = warp_m + 2 * 16 + (grp & 1) * 8 + rin;
                ldmatrix_x4(afrag[2][0], afrag[2][1], afrag[2][2], afrag[2][3],
                            &a_s[r2 * LDA + c]);
            }
#pragma unroll
            for (int nt = 0; nt < 4; nt++) mma_16816(acc[1][nt], afrag[1], bfrag[nt]);
            {
                int c = kbase + (grp >> 1) * 8;
                int r3 = warp_m + 3 * 16 + (grp & 1) * 8 + rin;
                ldmatrix_x4(afrag[3][0], afrag[3][1], afrag[3][2], afrag[3][3],
                            &a_s[r3 * LDA + c]);
            }
#pragma unroll
            for (int nt = 0; nt < 4; nt++) mma_16816(acc[2][nt], afrag[2], bfrag[nt]);
#pragma unroll
            for (int nt = 0; nt < 4; nt++) mma_16816(acc[3][nt], afrag[3], bfrag[nt]);
        }

        stage = (stage + 1 == NSTAGES) ? 0 : stage + 1;
    }

    // ---- epilogue: bf16-round(acc) + bf16 bias, store f32 (output dtype f32) ----
    const int tig = lane & 3;
    const int g8  = lane >> 2;
#pragma unroll
    for (int nt = 0; nt < 4; nt++) {
        int n = n0 + warp_n + nt * 8 + tig * 2;
        __nv_bfloat16 bb0 = __float2bfloat16(bias[n]);
        __nv_bfloat16 bb1 = __float2bfloat16(bias[n + 1]);
#pragma unroll
        for (int mt = 0; mt < 4; mt++) {
            int mA = m0 + warp_m + mt * 16 + g8;
            int mB = mA + 8;
            float2 v0, v1;
            v0.x = __bfloat162float(__hadd(__float2bfloat16(acc[mt][nt][0]), bb0));
            v0.y = __bfloat162float(__hadd(__float2bfloat16(acc[mt][nt][1]), bb1));
            v1.x = __bfloat162float(__hadd(__float2bfloat16(acc[mt][nt][2]), bb0));
            v1.y = __bfloat162float(__hadd(__float2bfloat16(acc[mt][nt][3]), bb1));
            *reinterpret_cast<float2*>(&out[(size_t)mA * NDIM + n]) = v0;
            *reinterpret_cast<float2*>(&out[(size_t)mB * NDIM + n]) = v1;
        }
    }
}

// ---------------------------------------------------------------------------
// Launch
// ---------------------------------------------------------------------------
extern "C" void kernel_launch(void* const* d_in, const int* in_sizes, int n_in,
                              void* d_out, int out_size) {
    const float* x     = (const float*)d_in[0];   // [B,S,IN] f32
    const float* w_fp8 = (const float*)d_in[1];   // [OUT,IN] f32
    const float* scale = (const float*)d_in[2];   // [OUT,1] f32
    const float* bias  = (const float*)d_in[3];   // [OUT] f32
    float* out         = (float*)d_out;           // [B,S,OUT] f32 (bf16-rounded values)

    int M = in_sizes[0] / KDIM;                   // 4096

    int c4x = (M * KDIM) / 4;
    int c4w = (NDIM * KDIM) / 4;
    int total4 = c4x + c4w;
    convert_all_kernel<<<(total4 + 255) / 256, 256>>>(x, w_fp8, scale, c4x, total4);

    cudaFuncSetAttribute(gemm_bf16_kernel,
                         cudaFuncAttributeMaxDynamicSharedMemorySize, SMEM_BYTES);
    dim3 grid(NDIM / BN, M / BM);   // (32, 32)
    gemm_bf16_kernel<<<grid, NTHREADS, SMEM_BYTES>>>(bias, out, M);
}

// round 16
// speedup vs baseline: 1.2670x; 1.0358x over previous
#include <cuda_runtime.h>
#include <cuda_bf16.h>
#include <cstdint>

// Problem shape (fixed): M = B*S = 4096, K = IN = 4096, N = OUT = 4096
#define KDIM 4096
#define NDIM 4096

#define BM 128
#define BN 64
#define BK 64
#define LDA 72      // BK + 8 halves pad -> 144B row stride, conflict-free for ldmatrix
#define NTHREADS 128
#define NSTAGES 2

#define TILE_A (BM * LDA)                  // 9216 halves
#define TILE_B (BN * LDA)                  // 4608 halves
#define STAGE_HALVES (TILE_A + TILE_B)     // 13824 halves = 27648 B
#define SMEM_BYTES (NSTAGES * STAGE_HALVES * 2)   // 55296 B -> 4 CTAs/SM

// Scratch: converted bf16 operands (device globals, not runtime allocs)
__device__ __nv_bfloat16 g_x_bf16[4096 * KDIM];
__device__ __nv_bfloat16 g_w_bf16[NDIM * KDIM];

// ---------------------------------------------------------------------------
// Merged preprocess: x (f32)->bf16 and w (f32)*scale->bf16 in ONE kernel
// ---------------------------------------------------------------------------
__global__ void convert_all_kernel(const float* __restrict__ x,
                                   const float* __restrict__ w,
                                   const float* __restrict__ scale,
                                   int c4x, int total4) {
    int i = blockIdx.x * blockDim.x + threadIdx.x;
    if (i >= total4) return;
    if (i < c4x) {
        float4 v = reinterpret_cast<const float4*>(x)[i];
        __nv_bfloat162 lo = __floats2bfloat162_rn(v.x, v.y);
        __nv_bfloat162 hi = __floats2bfloat162_rn(v.z, v.w);
        uint2 p;
        p.x = *reinterpret_cast<unsigned*>(&lo);
        p.y = *reinterpret_cast<unsigned*>(&hi);
        reinterpret_cast<uint2*>(g_x_bf16)[i] = p;
    } else {
        int j = i - c4x;
        int o = (j * 4) / KDIM;          // all 4 elems share a row (KDIM % 4 == 0)
        __nv_bfloat16 s = __float2bfloat16(scale[o]);
        float4 v = reinterpret_cast<const float4*>(w)[j];
        __nv_bfloat16 h0 = __hmul(__float2bfloat16(v.x), s);
        __nv_bfloat16 h1 = __hmul(__float2bfloat16(v.y), s);
        __nv_bfloat16 h2 = __hmul(__float2bfloat16(v.z), s);
        __nv_bfloat16 h3 = __hmul(__float2bfloat16(v.w), s);
        __nv_bfloat162 lo = __halves2bfloat162(h0, h1);
        __nv_bfloat162 hi = __halves2bfloat162(h2, h3);
        uint2 p;
        p.x = *reinterpret_cast<unsigned*>(&lo);
        p.y = *reinterpret_cast<unsigned*>(&hi);
        reinterpret_cast<uint2*>(g_w_bf16)[j] = p;
    }
}

// ---------------------------------------------------------------------------
// GEMM: C[M,N] = A[M,K] @ B[N,K]^T, bf16 in / f32 accum / f32 out (bf16-rounded)
// 128x64 CTA tile, 4 warps (64x32 each), 2-stage cp.async, 4 CTAs/SM
// -> 16 warps/SM in 4 independent barrier groups + halved wave granule.
// ---------------------------------------------------------------------------
__device__ __forceinline__ void cp_async16(void* smem_ptr, const void* gmem_ptr) {
    unsigned saddr = (unsigned)__cvta_generic_to_shared(smem_ptr);
    asm volatile("cp.async.cg.shared.global [%0], [%1], 16;\n" :: "r"(saddr), "l"(gmem_ptr));
}
__device__ __forceinline__ void cp_async_commit() {
    asm volatile("cp.async.commit_group;\n");
}
template <int N>
__device__ __forceinline__ void cp_async_wait() {
    asm volatile("cp.async.wait_group %0;\n" :: "n"(N));
}
__device__ __forceinline__ void ldmatrix_x4(unsigned& r0, unsigned& r1, unsigned& r2,
                                            unsigned& r3, const void* smem_ptr) {
    unsigned saddr = (unsigned)__cvta_generic_to_shared(smem_ptr);
    asm volatile("ldmatrix.sync.aligned.m8n8.x4.shared.b16 {%0,%1,%2,%3}, [%4];\n"
                 : "=r"(r0), "=r"(r1), "=r"(r2), "=r"(r3) : "r"(saddr));
}
__device__ __forceinline__ void mma_16816(float* c, const unsigned* a, const unsigned* b) {
    asm volatile(
        "mma.sync.aligned.m16n8k16.row.col.f32.bf16.bf16.f32 "
        "{%0,%1,%2,%3}, {%4,%5,%6,%7}, {%8,%9}, {%0,%1,%2,%3};\n"
        : "+f"(c[0]), "+f"(c[1]), "+f"(c[2]), "+f"(c[3])
        : "r"(a[0]), "r"(a[1]), "r"(a[2]), "r"(a[3]), "r"(b[0]), "r"(b[1]));
}

__global__ void __launch_bounds__(NTHREADS, 4)
gemm_bf16_kernel(const float* __restrict__ bias, float* __restrict__ out, int M) {
    extern __shared__ __align__(16) __nv_bfloat16 smem[];
    // stage s: A at smem[s*STAGE_HALVES], B at +TILE_A

    const int tid  = threadIdx.x;
    const int wid  = tid >> 5;
    const int lane = tid & 31;
    const int grp  = lane >> 3;       // 0..3 (ldmatrix address group)
    const int rin  = lane & 7;

    const int m0 = blockIdx.y * BM;
    const int n0 = blockIdx.x * BN;

    // warp tiling: 2 (m) x 2 (n) warps; each warp 64(m) x 32(n)
    const int warp_m = (wid >> 1) * 64;
    const int warp_n = (wid & 1) * 32;

    const __nv_bfloat16* A = g_x_bf16;
    const __nv_bfloat16* B = g_w_bf16;

    float acc[4][4][4];   // [mtile][ntile][frag] = 64 regs
#pragma unroll
    for (int i = 0; i < 4; i++)
#pragma unroll
        for (int j = 0; j < 4; j++)
#pragma unroll
            for (int r = 0; r < 4; r++) acc[i][j][r] = 0.0f;

    const int KTILES = KDIM / BK;   // 64

    // loader: A 1024 chunks (8/thread), B 512 chunks (4/thread), 16B each
    auto load_tile = [&](int stage, int kt) {
        __nv_bfloat16* sA = smem + stage * STAGE_HALVES;
        __nv_bfloat16* sB = sA + TILE_A;
#pragma unroll
        for (int j = 0; j < 8; j++) {
            int chunk = tid + j * NTHREADS;          // 0..1023
            int row = chunk >> 3;                    // 0..127
            int kc  = chunk & 7;
            cp_async16(&sA[row * LDA + kc * 8],
                       &A[(size_t)(m0 + row) * KDIM + kt * BK + kc * 8]);
        }
#pragma unroll
        for (int j = 0; j < 4; j++) {
            int chunk = tid + j * NTHREADS;          // 0..511
            int row = chunk >> 3;                    // 0..63
            int kc  = chunk & 7;
            cp_async16(&sB[row * LDA + kc * 8],
                       &B[(size_t)(n0 + row) * KDIM + kt * BK + kc * 8]);
        }
    };

    load_tile(0, 0);
    cp_async_commit();

    for (int kt = 0; kt < KTILES; kt++) {
        int cur = kt & 1;
        if (kt + 1 < KTILES) {
            load_tile(cur ^ 1, kt + 1);
            cp_async_commit();
            cp_async_wait<1>();
        } else {
            cp_async_wait<0>();
        }
        __syncthreads();

        const __nv_bfloat16* a_s = smem + cur * STAGE_HALVES;
        const __nv_bfloat16* b_s = a_s + TILE_A;

#pragma unroll
        for (int ks = 0; ks < 4; ks++) {
            const int kbase = ks * 16;

            // A fragments: 4 m-tiles of 16x16 (R8-verified ldmatrix mapping)
            unsigned afrag[4][4];
#pragma unroll
            for (int mt = 0; mt < 4; mt++) {
                int r = warp_m + mt * 16 + (grp & 1) * 8 + rin;
                int c = kbase + (grp >> 1) * 8;
                ldmatrix_x4(afrag[mt][0], afrag[mt][1], afrag[mt][2], afrag[mt][3],
                            &a_s[r * LDA + c]);
            }
            // B fragments: 4 n-tiles of 8(n)x16(k); 2 n-tiles per x4 (R8-verified)
            unsigned bfrag[4][2];
#pragma unroll
            for (int p = 0; p < 2; p++) {
                int nrow = warp_n + p * 16 + (grp >> 1) * 8 + rin;
                int c = kbase + (grp & 1) * 8;
                ldmatrix_x4(bfrag[2 * p][0], bfrag[2 * p][1],
                            bfrag[2 * p + 1][0], bfrag[2 * p + 1][1],
                            &b_s[nrow * LDA + c]);
            }
#pragma unroll
            for (int mt = 0; mt < 4; mt++)
#pragma unroll
                for (int nt = 0; nt < 4; nt++)
                    mma_16816(acc[mt][nt], afrag[mt], bfrag[nt]);
        }
        __syncthreads();
    }

    // ---- epilogue: bf16-round(acc) + bf16 bias, store f32 (output dtype f32) ----
    const int tig = lane & 3;
    const int g8  = lane >> 2;
#pragma unroll
    for (int nt = 0; nt < 4; nt++) {
        int n = n0 + warp_n + nt * 8 + tig * 2;
        __nv_bfloat16 bb0 = __float2bfloat16(bias[n]);
        __nv_bfloat16 bb1 = __float2bfloat16(bias[n + 1]);
#pragma unroll
        for (int mt = 0; mt < 4; mt++) {
            int mA = m0 + warp_m + mt * 16 + g8;
            int mB = mA + 8;
            float2 v0, v1;
            v0.x = __bfloat162float(__hadd(__float2bfloat16(acc[mt][nt][0]), bb0));
            v0.y = __bfloat162float(__hadd(__float2bfloat16(acc[mt][nt][1]), bb1));
            v1.x = __bfloat162float(__hadd(__float2bfloat16(acc[mt][nt][2]), bb0));
            v1.y = __bfloat162float(__hadd(__float2bfloat16(acc[mt][nt][3]), bb1));
            *reinterpret_cast<float2*>(&out[(size_t)mA * NDIM + n]) = v0;
            *reinterpret_cast<float2*>(&out[(size_t)mB * NDIM + n]) = v1;
        }
    }
}

// ---------------------------------------------------------------------------
// Launch
// ---------------------------------------------------------------------------
extern "C" void kernel_launch(void* const* d_in, const int* in_sizes, int n_in,
                              void* d_out, int out_size) {
    const float* x     = (const float*)d_in[0];   // [B,S,IN] f32
    const float* w_fp8 = (const float*)d_in[1];   // [OUT,IN] f32
    const float* scale = (const float*)d_in[2];   // [OUT,1] f32
    const float* bias  = (const float*)d_in[3];   // [OUT] f32
    float* out         = (float*)d_out;           // [B,S,OUT] f32 (bf16-rounded values)

    int M = in_sizes[0] / KDIM;                   // 4096

    int c4x = (M * KDIM) / 4;
    int c4w = (NDIM * KDIM) / 4;
    int total4 = c4x + c4w;
    convert_all_kernel<<<(total4 + 255) / 256, 256>>>(x, w_fp8, scale, c4x, total4);

    cudaFuncSetAttribute(gemm_bf16_kernel,
                         cudaFuncAttributeMaxDynamicSharedMemorySize, SMEM_BYTES);
    dim3 grid(NDIM / BN, M / BM);   // (64, 32) = 2048 CTAs
    gemm_bf16_kernel<<<grid, NTHREADS, SMEM_BYTES>>>(bias, out, M);
}